// round 4
// baseline (speedup 1.0000x reference)
#include <cuda_runtime.h>
#include <cuda_bf16.h>
#include <cstdint>

// ---------------------------------------------------------------------------
// SymbolicFeatureExtractor: per-row (seq_len, unique_count) -> 3 feats -> MLP.
// MLP output depends only on (seq_len, uniq) in [0,128]^2 -> 129x129x32 LUT
// (2.1 MB, L2-resident; inputs/outputs use streaming hints to protect it).
//
// Unique counting, atomic-free, no table clears:
//   Round 0 (double hash): every active token writes pack=(v<<7|pos) to TWO
//   slots of a 1024-entry per-warp table. After syncwarp it reads both back:
//     x = slot ^ pack;  x < 128  -> my value won that slot (cohort resolved;
//                                   the member with x==0 is the single winner)
//   Priority (check slot A before slot B) is value-consistent, so each
//   cohort counts exactly once. P(token unresolved) ~ 0.4%, so the fallback
//   loop (single fresh hash per round) runs for ~20% of rows only.
//   A token only ever reads slots it wrote in the same round -> stale data
//   is never observed; termination: the last writer of any written slot
//   always resolves, so >=1 cohort resolves per round.
// ---------------------------------------------------------------------------

#define MAX_LEN 128
#define LUT_DIM 129

__device__ float g_lut[LUT_DIM * LUT_DIM * 32];

__global__ __launch_bounds__(256)
void build_lut_kernel(const float* __restrict__ W1, const float* __restrict__ b1,
                      const float* __restrict__ W2, const float* __restrict__ b2) {
    int warp_in_block = threadIdx.x >> 5;
    int lane = threadIdx.x & 31;
    int idx = blockIdx.x * (blockDim.x >> 5) + warp_in_block;
    if (idx >= LUT_DIM * LUT_DIM) return;
    int s = idx / LUT_DIM;
    int u = idx % LUT_DIM;

    float f0 = (float)s * (1.0f / MAX_LEN);
    float f1 = (float)u * (1.0f / MAX_LEN);
    float f2 = (s > 0) ? ((float)u / (float)s) : 0.0f;

    float h = b1[lane];
    h = fmaf(f0, W1[0 * 32 + lane], h);
    h = fmaf(f1, W1[1 * 32 + lane], h);
    h = fmaf(f2, W1[2 * 32 + lane], h);
    h = fmaxf(h, 0.0f);

    float o = b2[lane];
    #pragma unroll
    for (int k = 0; k < 32; k++) {
        float hk = __shfl_sync(0xffffffffu, h, k);
        o = fmaf(hk, W2[k * 32 + lane], o);
    }
    g_lut[(size_t)idx * 32 + lane] = fmaxf(o, 0.0f);
}

#define WARPS_PER_BLOCK 8
#define HASH_BITS 10
#define HASH_SLOTS (1 << HASH_BITS)   // 1024 slots/warp, 32 KB/block

__global__ __launch_bounds__(WARPS_PER_BLOCK * 32)
void feat_kernel(const int* __restrict__ ids, const int* __restrict__ mask,
                 float* __restrict__ out, int B) {
    __shared__ int table[WARPS_PER_BLOCK][HASH_SLOTS];

    int w    = threadIdx.x >> 5;
    int lane = threadIdx.x & 31;
    int row  = blockIdx.x * WARPS_PER_BLOCK + w;
    if (row >= B) return;

    int* tab = table[w];

    const int4* idp = (const int4*)(ids  + (size_t)row * MAX_LEN);
    const int4* mkp = (const int4*)(mask + (size_t)row * MAX_LEN);
    int4 iv = __ldcs(idp + lane);     // streaming: keep LUT resident in L2
    int4 mv = __ldcs(mkp + lane);

    int seq = mv.x + mv.y + mv.z + mv.w;

    int vals[4] = {iv.x, iv.y, iv.z, iv.w};
    bool pend[4] = {mv.x != 0, mv.y != 0, mv.z != 0, mv.w != 0};

    unsigned h0[4];
    int pack[4];
    unsigned hA[4], hB[4];
    #pragma unroll
    for (int t = 0; t < 4; t++) {
        h0[t]   = (unsigned)vals[t] * 2654435761u;
        pack[t] = vals[t] * 128 + (lane * 4 + t);          // (v<<7)|pos
        hA[t]   = (h0[t] >> 22) & (HASH_SLOTS - 1);
        hB[t]   = (h0[t] >> 12) & (HASH_SLOTS - 1);
    }

    int cnt = 0;

    // ---- round 0: double-hash scatter ----
    #pragma unroll
    for (int t = 0; t < 4; t++)
        if (pend[t]) { tab[hA[t]] = pack[t]; tab[hB[t]] = pack[t]; }
    __syncwarp();
    #pragma unroll
    for (int t = 0; t < 4; t++) {
        if (pend[t]) {
            int x = tab[hA[t]] ^ pack[t];
            if (x < 128) {                      // value won slot A
                pend[t] = false;
                cnt += (x == 0);
            } else {
                x = tab[hB[t]] ^ pack[t];
                if (x < 128) {                  // value won slot B
                    pend[t] = false;
                    cnt += (x == 0);
                }
            }
        }
    }
    __syncwarp();

    // ---- rare fallback: fresh hash per round, survivors only (~20% of rows)
    while (__ballot_sync(0xffffffffu, pend[0] | pend[1] | pend[2] | pend[3])) {
        unsigned h[4];
        #pragma unroll
        for (int t = 0; t < 4; t++) {
            if (pend[t]) {
                h0[t] = (h0[t] ^ 0x85EBCA6Bu) * 2654435761u;
                h[t]  = (h0[t] >> 22) & (HASH_SLOTS - 1);
                tab[h[t]] = pack[t];
            }
        }
        __syncwarp();
        #pragma unroll
        for (int t = 0; t < 4; t++) {
            if (pend[t]) {
                int x = tab[h[t]] ^ pack[t];
                if (x < 128) { pend[t] = false; cnt += (x == 0); }
            }
        }
        __syncwarp();
    }

    seq = __reduce_add_sync(0xffffffffu, seq);
    cnt = __reduce_add_sync(0xffffffffu, cnt);

    float v = g_lut[((size_t)(seq * LUT_DIM + cnt)) * 32 + lane];
    __stcs(&out[(size_t)row * 32 + lane], v);
}

extern "C" void kernel_launch(void* const* d_in, const int* in_sizes, int n_in,
                              void* d_out, int out_size) {
    const int*   ids  = (const int*)d_in[0];
    const int*   mask = (const int*)d_in[1];
    const float* W1   = (const float*)d_in[2];
    const float* b1   = (const float*)d_in[3];
    const float* W2   = (const float*)d_in[4];
    const float* b2   = (const float*)d_in[5];
    float* out = (float*)d_out;

    int B = in_sizes[0] / MAX_LEN;

    int lut_pairs  = LUT_DIM * LUT_DIM;
    int lut_blocks = (lut_pairs + 7) / 8;
    build_lut_kernel<<<lut_blocks, 256>>>(W1, b1, W2, b2);

    int blocks = (B + WARPS_PER_BLOCK - 1) / WARPS_PER_BLOCK;
    feat_kernel<<<blocks, WARPS_PER_BLOCK * 32>>>(ids, mask, out, B);
}

// round 5
// speedup vs baseline: 1.0732x; 1.0732x over previous
#include <cuda_runtime.h>
#include <cuda_bf16.h>
#include <cstdint>

// ---------------------------------------------------------------------------
// SymbolicFeatureExtractor: per-row (seq_len, unique_count) -> 3 feats -> MLP.
// MLP output depends only on (seq_len, uniq) in [0,128]^2 -> 129x129x32 LUT
// (2.1 MB, L2-resident; inputs/outputs use streaming hints to protect it).
//
// Unique counting, atomic-free, no table clears, 512-slot per-warp table:
//   Round 0 (double hash, branch-free): every active token writes
//   pack=(v<<7|pos) to slots hA and hB; reads both back.
//     x = slot ^ pack; x < 128 -> my value won that slot (cohort resolved).
//   A-priority count rule: cnt += (xA==0) | (xA>=128 & xB==0); value-match
//   conditions are cohort-uniform, ownership (x==0) unique -> exactly once.
//   ~98% of tokens resolve here. Leftovers (~2/row) run a lockstep
//   rehash-per-round single-hash loop (same-value-wins logic stays exact;
//   last writer of a slot always resolves -> guaranteed termination).
//   Tokens only read slots written in the same round -> no stale reads.
// ---------------------------------------------------------------------------

#define MAX_LEN 128
#define LUT_DIM 129

__device__ float g_lut[LUT_DIM * LUT_DIM * 32];

__global__ __launch_bounds__(256)
void build_lut_kernel(const float* __restrict__ W1, const float* __restrict__ b1,
                      const float* __restrict__ W2, const float* __restrict__ b2) {
    int warp_in_block = threadIdx.x >> 5;
    int lane = threadIdx.x & 31;
    int idx = blockIdx.x * (blockDim.x >> 5) + warp_in_block;
    if (idx >= LUT_DIM * LUT_DIM) return;
    int s = idx / LUT_DIM;
    int u = idx % LUT_DIM;

    float f0 = (float)s * (1.0f / MAX_LEN);
    float f1 = (float)u * (1.0f / MAX_LEN);
    float f2 = (s > 0) ? ((float)u / (float)s) : 0.0f;

    float h = b1[lane];
    h = fmaf(f0, W1[0 * 32 + lane], h);
    h = fmaf(f1, W1[1 * 32 + lane], h);
    h = fmaf(f2, W1[2 * 32 + lane], h);
    h = fmaxf(h, 0.0f);

    float o = b2[lane];
    #pragma unroll
    for (int k = 0; k < 32; k++) {
        float hk = __shfl_sync(0xffffffffu, h, k);
        o = fmaf(hk, W2[k * 32 + lane], o);
    }
    g_lut[(size_t)idx * 32 + lane] = fmaxf(o, 0.0f);
}

#define WARPS_PER_BLOCK 8
#define HASH_BITS 9
#define HASH_SLOTS (1 << HASH_BITS)   // 512 slots/warp -> 16 KB/block

__global__ __launch_bounds__(WARPS_PER_BLOCK * 32)
void feat_kernel(const int* __restrict__ ids, const int* __restrict__ mask,
                 float* __restrict__ out, int B) {
    __shared__ int table[WARPS_PER_BLOCK][HASH_SLOTS];

    int w    = threadIdx.x >> 5;
    int lane = threadIdx.x & 31;
    int row  = blockIdx.x * WARPS_PER_BLOCK + w;
    if (row >= B) return;

    int* tab = table[w];

    const int4* idp = (const int4*)(ids  + (size_t)row * MAX_LEN);
    const int4* mkp = (const int4*)(mask + (size_t)row * MAX_LEN);
    int4 iv = __ldcs(idp + lane);     // streaming: keep LUT resident in L2
    int4 mv = __ldcs(mkp + lane);

    int seq = mv.x + mv.y + mv.z + mv.w;

    int vals[4] = {iv.x, iv.y, iv.z, iv.w};
    bool pend[4] = {mv.x != 0, mv.y != 0, mv.z != 0, mv.w != 0};

    unsigned h0[4];
    int pack[4];
    unsigned hA[4], hB[4];
    #pragma unroll
    for (int t = 0; t < 4; t++) {
        h0[t]   = (unsigned)vals[t] * 2654435761u;
        pack[t] = vals[t] * 128 + (lane * 4 + t);     // (v<<7)|pos
        hA[t]   = h0[t] >> (32 - HASH_BITS);
        hB[t]   = (h0[t] >> 14) & (HASH_SLOTS - 1);
    }

    int cnt = 0;

    // ---- round 0: double-hash scatter, branch-free resolve ----
    #pragma unroll
    for (int t = 0; t < 4; t++)
        if (pend[t]) { tab[hA[t]] = pack[t]; tab[hB[t]] = pack[t]; }
    __syncwarp();
    #pragma unroll
    for (int t = 0; t < 4; t++) {
        if (pend[t]) {
            int xA = tab[hA[t]] ^ pack[t];     // two independent LDS, overlapped
            int xB = tab[hB[t]] ^ pack[t];
            bool mA = (unsigned)xA < 128u;     // value won slot A
            bool mB = (unsigned)xB < 128u;     // value won slot B
            pend[t] = !(mA | mB);
            cnt += (xA == 0) | ((!mA) & (xB == 0));
        }
    }
    __syncwarp();

    // ---- thin fallback: fresh hash per round, ~2 tokens/row active ----
    while (__ballot_sync(0xffffffffu, pend[0] | pend[1] | pend[2] | pend[3])) {
        unsigned h[4];
        #pragma unroll
        for (int t = 0; t < 4; t++) {
            if (pend[t]) {
                h0[t] = (h0[t] ^ 0x85EBCA6Bu) * 2654435761u;
                h[t]  = h0[t] >> (32 - HASH_BITS);
                tab[h[t]] = pack[t];
            }
        }
        __syncwarp();
        #pragma unroll
        for (int t = 0; t < 4; t++) {
            if (pend[t]) {
                int x = tab[h[t]] ^ pack[t];
                if ((unsigned)x < 128u) { pend[t] = false; cnt += (x == 0); }
            }
        }
        __syncwarp();
    }

    seq = __reduce_add_sync(0xffffffffu, seq);
    cnt = __reduce_add_sync(0xffffffffu, cnt);

    float v = g_lut[((size_t)(seq * LUT_DIM + cnt)) * 32 + lane];
    __stcs(&out[(size_t)row * 32 + lane], v);
}

extern "C" void kernel_launch(void* const* d_in, const int* in_sizes, int n_in,
                              void* d_out, int out_size) {
    const int*   ids  = (const int*)d_in[0];
    const int*   mask = (const int*)d_in[1];
    const float* W1   = (const float*)d_in[2];
    const float* b1   = (const float*)d_in[3];
    const float* W2   = (const float*)d_in[4];
    const float* b2   = (const float*)d_in[5];
    float* out = (float*)d_out;

    int B = in_sizes[0] / MAX_LEN;

    int lut_pairs  = LUT_DIM * LUT_DIM;
    int lut_blocks = (lut_pairs + 7) / 8;
    build_lut_kernel<<<lut_blocks, 256>>>(W1, b1, W2, b2);

    int blocks = (B + WARPS_PER_BLOCK - 1) / WARPS_PER_BLOCK;
    feat_kernel<<<blocks, WARPS_PER_BLOCK * 32>>>(ids, mask, out, B);
}

// round 6
// speedup vs baseline: 1.2225x; 1.1392x over previous
#include <cuda_runtime.h>
#include <cuda_bf16.h>
#include <cstdint>

// ---------------------------------------------------------------------------
// SymbolicFeatureExtractor: per-row (seq_len, unique_count) -> 3 feats -> MLP.
// MLP output depends only on (seq_len, uniq) in [0,128]^2 -> 129x129x32 LUT
// (2.1 MB, L2-resident; inputs/outputs use streaming hints to protect it).
//
// Unique counting, atomic-free, no clears:
//   Phase 1 (single hash, 512-slot per-warp table): active tokens write
//   pack=(v<<7|pos) to tab[h(v)], syncwarp, read back.
//     x = slot ^ pack; x < 128 -> my value won the slot (cohort resolved;
//     the member with x==0 is the unique winner and counts 1).
//   Survivors are cohort-closed: all copies of a value hash to the same slot,
//   so a value's tokens resolve or survive together (~4 survivors/row).
//   Phase 2 (no smem): ballot-elect a leader among lanes with pending
//   tokens; leader broadcasts one pending value; all lanes clear matching
//   tokens; leader counts 1. One cohort retired per iteration -> exact,
//   deterministic, terminating.
// ---------------------------------------------------------------------------

#define MAX_LEN 128
#define LUT_DIM 129

__device__ float g_lut[LUT_DIM * LUT_DIM * 32];

__global__ __launch_bounds__(256)
void build_lut_kernel(const float* __restrict__ W1, const float* __restrict__ b1,
                      const float* __restrict__ W2, const float* __restrict__ b2) {
    int warp_in_block = threadIdx.x >> 5;
    int lane = threadIdx.x & 31;
    int idx = blockIdx.x * (blockDim.x >> 5) + warp_in_block;
    if (idx >= LUT_DIM * LUT_DIM) return;
    int s = idx / LUT_DIM;
    int u = idx % LUT_DIM;

    float f0 = (float)s * (1.0f / MAX_LEN);
    float f1 = (float)u * (1.0f / MAX_LEN);
    float f2 = (s > 0) ? ((float)u / (float)s) : 0.0f;

    float h = b1[lane];
    h = fmaf(f0, W1[0 * 32 + lane], h);
    h = fmaf(f1, W1[1 * 32 + lane], h);
    h = fmaf(f2, W1[2 * 32 + lane], h);
    h = fmaxf(h, 0.0f);

    float o = b2[lane];
    #pragma unroll
    for (int k = 0; k < 32; k++) {
        float hk = __shfl_sync(0xffffffffu, h, k);
        o = fmaf(hk, W2[k * 32 + lane], o);
    }
    g_lut[(size_t)idx * 32 + lane] = fmaxf(o, 0.0f);
}

#define WARPS_PER_BLOCK 8
#define HASH_BITS 9
#define HASH_SLOTS (1 << HASH_BITS)   // 512 slots/warp -> 16 KB/block

__global__ __launch_bounds__(WARPS_PER_BLOCK * 32)
void feat_kernel(const int* __restrict__ ids, const int* __restrict__ mask,
                 float* __restrict__ out, int B) {
    __shared__ int table[WARPS_PER_BLOCK][HASH_SLOTS];

    int w    = threadIdx.x >> 5;
    int lane = threadIdx.x & 31;
    int row  = blockIdx.x * WARPS_PER_BLOCK + w;
    if (row >= B) return;

    int* tab = table[w];

    const int4* idp = (const int4*)(ids  + (size_t)row * MAX_LEN);
    const int4* mkp = (const int4*)(mask + (size_t)row * MAX_LEN);
    int4 iv = __ldcs(idp + lane);     // streaming: keep LUT resident in L2
    int4 mv = __ldcs(mkp + lane);

    int seq = mv.x + mv.y + mv.z + mv.w;

    int vals[4] = {iv.x, iv.y, iv.z, iv.w};
    bool pend[4] = {mv.x != 0, mv.y != 0, mv.z != 0, mv.w != 0};

    unsigned h[4];
    int pack[4];
    #pragma unroll
    for (int t = 0; t < 4; t++) {
        h[t]    = ((unsigned)vals[t] * 2654435761u) >> (32 - HASH_BITS);
        pack[t] = vals[t] * 128 + (lane * 4 + t);     // (v<<7)|pos
    }

    int cnt = 0;

    // ---- phase 1: single-hash scatter ----
    #pragma unroll
    for (int t = 0; t < 4; t++)
        if (pend[t]) tab[h[t]] = pack[t];
    __syncwarp();
    #pragma unroll
    for (int t = 0; t < 4; t++) {
        if (pend[t]) {
            int x = tab[h[t]] ^ pack[t];
            if ((unsigned)x < 128u) {          // my value won -> cohort resolved
                pend[t] = false;
                cnt += (x == 0);               // unique last-writer counts
            }
        }
    }

    // ---- phase 2: smem-free cohort broadcast (~4 iterations/row) ----
    while (true) {
        bool any = pend[0] | pend[1] | pend[2] | pend[3];
        unsigned m = __ballot_sync(0xffffffffu, any);
        if (!m) break;
        int leader = __ffs(m) - 1;
        int myv = pend[0] ? vals[0] : pend[1] ? vals[1]
                : pend[2] ? vals[2] : vals[3];
        int lv = __shfl_sync(0xffffffffu, myv, leader);
        cnt += (lane == leader);               // exactly one lane counts cohort
        #pragma unroll
        for (int t = 0; t < 4; t++)
            pend[t] &= (vals[t] != lv);
    }

    seq = __reduce_add_sync(0xffffffffu, seq);
    cnt = __reduce_add_sync(0xffffffffu, cnt);

    float v = g_lut[((size_t)(seq * LUT_DIM + cnt)) * 32 + lane];
    __stcs(&out[(size_t)row * 32 + lane], v);
}

extern "C" void kernel_launch(void* const* d_in, const int* in_sizes, int n_in,
                              void* d_out, int out_size) {
    const int*   ids  = (const int*)d_in[0];
    const int*   mask = (const int*)d_in[1];
    const float* W1   = (const float*)d_in[2];
    const float* b1   = (const float*)d_in[3];
    const float* W2   = (const float*)d_in[4];
    const float* b2   = (const float*)d_in[5];
    float* out = (float*)d_out;

    int B = in_sizes[0] / MAX_LEN;

    int lut_pairs  = LUT_DIM * LUT_DIM;
    int lut_blocks = (lut_pairs + 7) / 8;
    build_lut_kernel<<<lut_blocks, 256>>>(W1, b1, W2, b2);

    int blocks = (B + WARPS_PER_BLOCK - 1) / WARPS_PER_BLOCK;
    feat_kernel<<<blocks, WARPS_PER_BLOCK * 32>>>(ids, mask, out, B);
}

// round 7
// speedup vs baseline: 1.2898x; 1.0550x over previous
#include <cuda_runtime.h>
#include <cuda_bf16.h>
#include <cstdint>

// ---------------------------------------------------------------------------
// SymbolicFeatureExtractor: per-row (seq_len, unique_count) -> 3 feats -> MLP.
// MLP output depends only on (seq_len, uniq) in [0,128]^2 -> 129x129x32 LUT
// (2.1 MB, L2-resident; inputs/outputs use streaming hints to protect it).
//
// Unique counting, atomic-free, no clears, 512-slot per-warp table:
//   Round 0 (direct-mapped, idx = v & 511): active tokens write
//   pack=(v<<7|pos); read back; x = slot^pack; x<128 -> my value won the
//   slot (cohort resolved; the x==0 member is the unique winner, counts 1).
//   Survivors are cohort-closed (same value -> same slot -> resolve/survive
//   together). ~4 survivors/row.
//   Round 1 (multiplicative hash, straight-line predicated): same protocol
//   on survivors only. ~0.06 unresolved tokens/row remain.
//   Tail: ballot-elect broadcast loop (exact; ~always 0 iterations).
//   Safety: a token only reads a slot it wrote in the same round (its own
//   write overlays any stale content; post-sync content is some same-round
//   writer's pack), so no initialization/clears are ever needed.
// ---------------------------------------------------------------------------

#define MAX_LEN 128
#define LUT_DIM 129

__device__ float g_lut[LUT_DIM * LUT_DIM * 32];

__global__ __launch_bounds__(256)
void build_lut_kernel(const float* __restrict__ W1, const float* __restrict__ b1,
                      const float* __restrict__ W2, const float* __restrict__ b2) {
    int warp_in_block = threadIdx.x >> 5;
    int lane = threadIdx.x & 31;
    int idx = blockIdx.x * (blockDim.x >> 5) + warp_in_block;
    if (idx >= LUT_DIM * LUT_DIM) return;
    int s = idx / LUT_DIM;
    int u = idx % LUT_DIM;

    float f0 = (float)s * (1.0f / MAX_LEN);
    float f1 = (float)u * (1.0f / MAX_LEN);
    float f2 = (s > 0) ? ((float)u / (float)s) : 0.0f;

    float h = b1[lane];
    h = fmaf(f0, W1[0 * 32 + lane], h);
    h = fmaf(f1, W1[1 * 32 + lane], h);
    h = fmaf(f2, W1[2 * 32 + lane], h);
    h = fmaxf(h, 0.0f);

    float o = b2[lane];
    #pragma unroll
    for (int k = 0; k < 32; k++) {
        float hk = __shfl_sync(0xffffffffu, h, k);
        o = fmaf(hk, W2[k * 32 + lane], o);
    }
    g_lut[(size_t)idx * 32 + lane] = fmaxf(o, 0.0f);
}

#define WARPS_PER_BLOCK 8
#define HASH_SLOTS 512      // 16 KB/block

__global__ __launch_bounds__(WARPS_PER_BLOCK * 32)
void feat_kernel(const int* __restrict__ ids, const int* __restrict__ mask,
                 float* __restrict__ out, int B) {
    __shared__ int table[WARPS_PER_BLOCK][HASH_SLOTS];

    int w    = threadIdx.x >> 5;
    int lane = threadIdx.x & 31;
    int row  = blockIdx.x * WARPS_PER_BLOCK + w;
    if (row >= B) return;

    int* tab = table[w];

    const int4* idp = (const int4*)(ids  + (size_t)row * MAX_LEN);
    const int4* mkp = (const int4*)(mask + (size_t)row * MAX_LEN);
    int4 iv = __ldcs(idp + lane);     // streaming: keep LUT resident in L2
    int4 mv = __ldcs(mkp + lane);

    int seq = mv.x + mv.y + mv.z + mv.w;

    int vals[4] = {iv.x, iv.y, iv.z, iv.w};
    bool pend[4] = {mv.x != 0, mv.y != 0, mv.z != 0, mv.w != 0};

    int pack[4];
    int lane4 = lane * 4;
    #pragma unroll
    for (int t = 0; t < 4; t++)
        pack[t] = vals[t] * 128 + (lane4 + t);       // (v<<7)|pos

    int cnt = 0;

    // ---- round 0: direct-mapped scatter (idx = v & 511) ----
    unsigned h[4];
    #pragma unroll
    for (int t = 0; t < 4; t++) {
        h[t] = (unsigned)vals[t] & (HASH_SLOTS - 1);
        if (pend[t]) tab[h[t]] = pack[t];
    }
    __syncwarp();
    #pragma unroll
    for (int t = 0; t < 4; t++) {
        if (pend[t]) {
            int x = tab[h[t]] ^ pack[t];
            if ((unsigned)x < 128u) { pend[t] = false; cnt += (x == 0); }
        }
    }
    __syncwarp();   // round-1 writes must not clobber slots mid-read

    // ---- round 1: multiplicative-hash rescatter, survivors only (~4/row) --
    #pragma unroll
    for (int t = 0; t < 4; t++) {
        if (pend[t]) {
            h[t] = ((unsigned)vals[t] * 2654435761u) >> 23;   // 9 bits
            tab[h[t]] = pack[t];
        }
    }
    __syncwarp();
    #pragma unroll
    for (int t = 0; t < 4; t++) {
        if (pend[t]) {
            int x = tab[h[t]] ^ pack[t];
            if ((unsigned)x < 128u) { pend[t] = false; cnt += (x == 0); }
        }
    }

    // ---- tail: smem-free cohort broadcast (~0 iterations typical) ----
    while (true) {
        bool any = pend[0] | pend[1] | pend[2] | pend[3];
        unsigned m = __ballot_sync(0xffffffffu, any);
        if (!m) break;
        int leader = __ffs(m) - 1;
        int myv = pend[0] ? vals[0] : pend[1] ? vals[1]
                : pend[2] ? vals[2] : vals[3];
        int lv = __shfl_sync(0xffffffffu, myv, leader);
        cnt += (lane == leader);
        #pragma unroll
        for (int t = 0; t < 4; t++)
            pend[t] &= (vals[t] != lv);
    }

    seq = __reduce_add_sync(0xffffffffu, seq);
    cnt = __reduce_add_sync(0xffffffffu, cnt);

    float v = g_lut[((size_t)(seq * LUT_DIM + cnt)) * 32 + lane];
    __stcs(&out[(size_t)row * 32 + lane], v);
}

extern "C" void kernel_launch(void* const* d_in, const int* in_sizes, int n_in,
                              void* d_out, int out_size) {
    const int*   ids  = (const int*)d_in[0];
    const int*   mask = (const int*)d_in[1];
    const float* W1   = (const float*)d_in[2];
    const float* b1   = (const float*)d_in[3];
    const float* W2   = (const float*)d_in[4];
    const float* b2   = (const float*)d_in[5];
    float* out = (float*)d_out;

    int B = in_sizes[0] / MAX_LEN;

    int lut_pairs  = LUT_DIM * LUT_DIM;
    int lut_blocks = (lut_pairs + 7) / 8;
    build_lut_kernel<<<lut_blocks, 256>>>(W1, b1, W2, b2);

    int blocks = (B + WARPS_PER_BLOCK - 1) / WARPS_PER_BLOCK;
    feat_kernel<<<blocks, WARPS_PER_BLOCK * 32>>>(ids, mask, out, B);
}

// round 8
// speedup vs baseline: 1.3137x; 1.0185x over previous
#include <cuda_runtime.h>
#include <cuda_bf16.h>
#include <cstdint>

// ---------------------------------------------------------------------------
// SymbolicFeatureExtractor: per-row (seq_len, unique_count) -> 3 feats -> MLP.
// MLP output depends only on (seq_len, uniq) in [0,128]^2 -> 129x129x32 LUT
// (2.1 MB, L2-resident; inputs/outputs use streaming hints to protect it).
//
// Unique counting, atomic-free, no clears, 512-slot per-warp table:
//   Round 0 (direct-mapped, idx = v & 511): active tokens write
//   pack=(v<<7|pos); read back; x = slot^pack; x<128 -> my value won the
//   slot (cohort resolved; the x==0 member is the unique winner, counts 1).
//   Round 1 (multiplicative hash): same protocol on survivors (~4/row).
//   Tail: ballot-elect cohort broadcast loop (exact, ~0 iterations typical).
//
//   NOTE: there is deliberately NO syncwarp between round-0 reads and
//   round-1 writes. A late round-0 reader observing a round-1 pack either
//   sees a different value (stays pending, handled later) or its own value
//   with another token's pos (resolves WITHOUT counting; the cohort is still
//   counted exactly once by the round-1 winner or the tail loop). The sync
//   after round-1 writes IS required (ordering writes before reads keeps the
//   count-iff-own-pack rule single-winner).
// ---------------------------------------------------------------------------

#define MAX_LEN 128
#define LUT_DIM 129

__device__ float g_lut[LUT_DIM * LUT_DIM * 32];

#define LUT_PAIRS_PER_WARP 8

__global__ __launch_bounds__(256)
void build_lut_kernel(const float* __restrict__ W1, const float* __restrict__ b1,
                      const float* __restrict__ W2, const float* __restrict__ b2) {
    int warp_in_block = threadIdx.x >> 5;
    int lane = threadIdx.x & 31;
    int base = (blockIdx.x * (blockDim.x >> 5) + warp_in_block) * LUT_PAIRS_PER_WARP;
    if (base >= LUT_DIM * LUT_DIM) return;

    // Hoist all weights into registers; reused across 8 pairs.
    float w10 = W1[0 * 32 + lane];
    float w11 = W1[1 * 32 + lane];
    float w12 = W1[2 * 32 + lane];
    float bb1 = b1[lane];
    float bb2 = b2[lane];
    float w2c[32];
    #pragma unroll
    for (int k = 0; k < 32; k++) w2c[k] = W2[k * 32 + lane];

    #pragma unroll
    for (int p = 0; p < LUT_PAIRS_PER_WARP; p++) {
        int idx = base + p;
        if (idx >= LUT_DIM * LUT_DIM) break;
        int s = idx / LUT_DIM;
        int u = idx % LUT_DIM;

        float f0 = (float)s * (1.0f / MAX_LEN);
        float f1 = (float)u * (1.0f / MAX_LEN);
        float f2 = (s > 0) ? ((float)u / (float)s) : 0.0f;

        float h = bb1;
        h = fmaf(f0, w10, h);
        h = fmaf(f1, w11, h);
        h = fmaf(f2, w12, h);
        h = fmaxf(h, 0.0f);

        float o = bb2;
        #pragma unroll
        for (int k = 0; k < 32; k++) {
            float hk = __shfl_sync(0xffffffffu, h, k);
            o = fmaf(hk, w2c[k], o);
        }
        g_lut[(size_t)idx * 32 + lane] = fmaxf(o, 0.0f);
    }
}

#define WARPS_PER_BLOCK 8
#define HASH_SLOTS 512      // 16 KB/block -> 8 blocks/SM, 64 warps

__global__ __launch_bounds__(WARPS_PER_BLOCK * 32)
void feat_kernel(const int* __restrict__ ids, const int* __restrict__ mask,
                 float* __restrict__ out, int B) {
    __shared__ int table[WARPS_PER_BLOCK][HASH_SLOTS];

    int w    = threadIdx.x >> 5;
    int lane = threadIdx.x & 31;
    int row  = blockIdx.x * WARPS_PER_BLOCK + w;
    if (row >= B) return;

    int* tab = table[w];

    const int4* idp = (const int4*)(ids  + (size_t)row * MAX_LEN);
    const int4* mkp = (const int4*)(mask + (size_t)row * MAX_LEN);
    int4 iv = __ldcs(idp + lane);     // streaming: keep LUT resident in L2
    int4 mv = __ldcs(mkp + lane);

    int seq = mv.x + mv.y + mv.z + mv.w;

    int vals[4] = {iv.x, iv.y, iv.z, iv.w};
    bool pend[4] = {mv.x != 0, mv.y != 0, mv.z != 0, mv.w != 0};

    int pack[4];
    int lane4 = lane * 4;
    #pragma unroll
    for (int t = 0; t < 4; t++)
        pack[t] = vals[t] * 128 + (lane4 + t);       // (v<<7)|pos

    int cnt = 0;

    // ---- round 0: direct-mapped scatter (idx = v & 511) ----
    unsigned h[4];
    #pragma unroll
    for (int t = 0; t < 4; t++) {
        h[t] = (unsigned)vals[t] & (HASH_SLOTS - 1);
        if (pend[t]) tab[h[t]] = pack[t];
    }
    __syncwarp();
    #pragma unroll
    for (int t = 0; t < 4; t++) {
        if (pend[t]) {
            int x = tab[h[t]] ^ pack[t];
            if ((unsigned)x < 128u) { pend[t] = false; cnt += (x == 0); }
        }
    }
    // (no syncwarp here -- see header comment; safe by exactly-once analysis)

    // ---- round 1: multiplicative-hash rescatter, survivors only (~4/row) --
    #pragma unroll
    for (int t = 0; t < 4; t++) {
        if (pend[t]) {
            h[t] = ((unsigned)vals[t] * 2654435761u) >> 23;   // 9 bits
            tab[h[t]] = pack[t];
        }
    }
    __syncwarp();   // REQUIRED: all round-1 writes before any round-1 read
    #pragma unroll
    for (int t = 0; t < 4; t++) {
        if (pend[t]) {
            int x = tab[h[t]] ^ pack[t];
            if ((unsigned)x < 128u) { pend[t] = false; cnt += (x == 0); }
        }
    }

    // ---- tail: smem-free cohort broadcast (~0 iterations typical) ----
    while (true) {
        bool any = pend[0] | pend[1] | pend[2] | pend[3];
        unsigned m = __ballot_sync(0xffffffffu, any);
        if (!m) break;
        int leader = __ffs(m) - 1;
        int myv = pend[0] ? vals[0] : pend[1] ? vals[1]
                : pend[2] ? vals[2] : vals[3];
        int lv = __shfl_sync(0xffffffffu, myv, leader);
        cnt += (lane == leader);
        #pragma unroll
        for (int t = 0; t < 4; t++)
            pend[t] &= (vals[t] != lv);
    }

    // Fused reduction: LUT row index = seq*129 + cnt is linear in per-lane
    // partials, so one REDUX computes it directly.
    int idx = __reduce_add_sync(0xffffffffu, seq * LUT_DIM + cnt);

    float v = g_lut[(size_t)idx * 32 + lane];
    __stcs(&out[(size_t)row * 32 + lane], v);
}

extern "C" void kernel_launch(void* const* d_in, const int* in_sizes, int n_in,
                              void* d_out, int out_size) {
    const int*   ids  = (const int*)d_in[0];
    const int*   mask = (const int*)d_in[1];
    const float* W1   = (const float*)d_in[2];
    const float* b1   = (const float*)d_in[3];
    const float* W2   = (const float*)d_in[4];
    const float* b2   = (const float*)d_in[5];
    float* out = (float*)d_out;

    int B = in_sizes[0] / MAX_LEN;

    int lut_pairs  = LUT_DIM * LUT_DIM;
    int pairs_per_block = 8 * LUT_PAIRS_PER_WARP;   // 8 warps x 8 pairs
    int lut_blocks = (lut_pairs + pairs_per_block - 1) / pairs_per_block;
    build_lut_kernel<<<lut_blocks, 256>>>(W1, b1, W2, b2);

    int blocks = (B + WARPS_PER_BLOCK - 1) / WARPS_PER_BLOCK;
    feat_kernel<<<blocks, WARPS_PER_BLOCK * 32>>>(ids, mask, out, B);
}

// round 9
// speedup vs baseline: 1.4028x; 1.0678x over previous
#include <cuda_runtime.h>
#include <cuda_bf16.h>
#include <cstdint>

// ---------------------------------------------------------------------------
// SymbolicFeatureExtractor: per-row (seq_len, unique_count) -> 3 feats -> MLP.
// MLP output depends only on (seq_len, uniq) in [0,128]^2 -> 129x129x32 LUT
// (2.1 MB, L2-resident; inputs/outputs use streaming hints to protect it).
//
// R9: TWO rows per warp. All 4 input LDG.128 front-batched (MLP 4), then the
// two rows run sequentially through the same 512-slot per-warp table.
// Safety (no clears, no cross-row pollution): in every round a token WRITES
// its slot before READING it, and all same-round writes precede all reads of
// that round (syncwarp). Hence a read always observes some same-round,
// same-row writer's pack -- never stale content from a prior round or row.
//
// Per-row protocol (identical to R8):
//   Round 0 (direct-mapped, idx = v & 511): write pack=(v<<7|pos), read back;
//   x = slot^pack; x<128 -> my value won (cohort resolved; x==0 member is
//   the unique winner, counts 1). Round 1 (multiplicative hash) on the ~7
//   survivors. Tail: ballot-elect cohort broadcast (exact, ~0 iters).
// ---------------------------------------------------------------------------

#define MAX_LEN 128
#define LUT_DIM 129

__device__ float g_lut[LUT_DIM * LUT_DIM * 32];

#define LUT_PAIRS_PER_WARP 8

__global__ __launch_bounds__(256)
void build_lut_kernel(const float* __restrict__ W1, const float* __restrict__ b1,
                      const float* __restrict__ W2, const float* __restrict__ b2) {
    int warp_in_block = threadIdx.x >> 5;
    int lane = threadIdx.x & 31;
    int base = (blockIdx.x * (blockDim.x >> 5) + warp_in_block) * LUT_PAIRS_PER_WARP;
    if (base >= LUT_DIM * LUT_DIM) return;

    float w10 = W1[0 * 32 + lane];
    float w11 = W1[1 * 32 + lane];
    float w12 = W1[2 * 32 + lane];
    float bb1 = b1[lane];
    float bb2 = b2[lane];
    float w2c[32];
    #pragma unroll
    for (int k = 0; k < 32; k++) w2c[k] = W2[k * 32 + lane];

    #pragma unroll
    for (int p = 0; p < LUT_PAIRS_PER_WARP; p++) {
        int idx = base + p;
        if (idx >= LUT_DIM * LUT_DIM) break;
        int s = idx / LUT_DIM;
        int u = idx % LUT_DIM;

        float f0 = (float)s * (1.0f / MAX_LEN);
        float f1 = (float)u * (1.0f / MAX_LEN);
        float f2 = (s > 0) ? ((float)u / (float)s) : 0.0f;

        float h = bb1;
        h = fmaf(f0, w10, h);
        h = fmaf(f1, w11, h);
        h = fmaf(f2, w12, h);
        h = fmaxf(h, 0.0f);

        float o = bb2;
        #pragma unroll
        for (int k = 0; k < 32; k++) {
            float hk = __shfl_sync(0xffffffffu, h, k);
            o = fmaf(hk, w2c[k], o);
        }
        g_lut[(size_t)idx * 32 + lane] = fmaxf(o, 0.0f);
    }
}

#define WARPS_PER_BLOCK 8
#define ROWS_PER_WARP 2
#define HASH_SLOTS 512      // 16 KB/block

// Count uniques for one row's 4 tokens; tab is the warp-private table.
// Returns per-lane partial count.
__device__ __forceinline__ int count_uniques(int* tab, const int4& iv,
                                             const int4& mv, int lane) {
    int vals[4] = {iv.x, iv.y, iv.z, iv.w};
    bool pend[4] = {mv.x != 0, mv.y != 0, mv.z != 0, mv.w != 0};

    int lane4 = lane * 4;
    int pack[4];
    #pragma unroll
    for (int t = 0; t < 4; t++)
        pack[t] = vals[t] * 128 + (lane4 + t);   // (v<<7)|pos

    int cnt = 0;
    unsigned h[4];

    // round 0: direct-mapped
    #pragma unroll
    for (int t = 0; t < 4; t++) {
        h[t] = (unsigned)vals[t] & (HASH_SLOTS - 1);
        if (pend[t]) tab[h[t]] = pack[t];
    }
    __syncwarp();
    #pragma unroll
    for (int t = 0; t < 4; t++) {
        if (pend[t]) {
            int x = tab[h[t]] ^ pack[t];
            if ((unsigned)x < 128u) { pend[t] = false; cnt += (x == 0); }
        }
    }
    __syncwarp();   // round-0 reads complete before round-1 writes

    // round 1: multiplicative hash, survivors only
    #pragma unroll
    for (int t = 0; t < 4; t++) {
        if (pend[t]) {
            h[t] = ((unsigned)vals[t] * 2654435761u) >> 23;
            tab[h[t]] = pack[t];
        }
    }
    __syncwarp();
    #pragma unroll
    for (int t = 0; t < 4; t++) {
        if (pend[t]) {
            int x = tab[h[t]] ^ pack[t];
            if ((unsigned)x < 128u) { pend[t] = false; cnt += (x == 0); }
        }
    }
    __syncwarp();   // row isolation: all reads done before next row's writes

    // tail: smem-free cohort broadcast
    while (true) {
        bool any = pend[0] | pend[1] | pend[2] | pend[3];
        unsigned m = __ballot_sync(0xffffffffu, any);
        if (!m) break;
        int leader = __ffs(m) - 1;
        int myv = pend[0] ? vals[0] : pend[1] ? vals[1]
                : pend[2] ? vals[2] : vals[3];
        int lv = __shfl_sync(0xffffffffu, myv, leader);
        cnt += (lane == leader);
        #pragma unroll
        for (int t = 0; t < 4; t++)
            pend[t] &= (vals[t] != lv);
    }
    return cnt;
}

__global__ __launch_bounds__(WARPS_PER_BLOCK * 32, 6)
void feat_kernel(const int* __restrict__ ids, const int* __restrict__ mask,
                 float* __restrict__ out, int B) {
    __shared__ int table[WARPS_PER_BLOCK][HASH_SLOTS];

    int w    = threadIdx.x >> 5;
    int lane = threadIdx.x & 31;
    int row0 = (blockIdx.x * WARPS_PER_BLOCK + w) * ROWS_PER_WARP;
    if (row0 >= B) return;
    int row1 = row0 + 1;
    bool has1 = row1 < B;

    int* tab = table[w];

    // Front-batch all 4 input loads (MLP 4, streaming to protect L2 LUT).
    const int4* id0 = (const int4*)(ids  + (size_t)row0 * MAX_LEN);
    const int4* mk0 = (const int4*)(mask + (size_t)row0 * MAX_LEN);
    const int4* id1 = (const int4*)(ids  + (size_t)row1 * MAX_LEN);
    const int4* mk1 = (const int4*)(mask + (size_t)row1 * MAX_LEN);
    int4 iv0 = __ldcs(id0 + lane);
    int4 mv0 = __ldcs(mk0 + lane);
    int4 iv1, mv1;
    if (has1) { iv1 = __ldcs(id1 + lane); mv1 = __ldcs(mk1 + lane); }
    else      { iv1 = make_int4(0,0,0,0); mv1 = make_int4(0,0,0,0); }

    int seq0 = mv0.x + mv0.y + mv0.z + mv0.w;
    int seq1 = mv1.x + mv1.y + mv1.z + mv1.w;

    int cnt0 = count_uniques(tab, iv0, mv0, lane);
    int cnt1 = count_uniques(tab, iv1, mv1, lane);

    // LUT index is linear in per-lane partials: one REDUX per row.
    int idx0 = __reduce_add_sync(0xffffffffu, seq0 * LUT_DIM + cnt0);
    int idx1 = __reduce_add_sync(0xffffffffu, seq1 * LUT_DIM + cnt1);

    // Batched gathers (two overlapped L2 hits), then stores.
    float v0 = g_lut[(size_t)idx0 * 32 + lane];
    float v1 = g_lut[(size_t)idx1 * 32 + lane];
    __stcs(&out[(size_t)row0 * 32 + lane], v0);
    if (has1) __stcs(&out[(size_t)row1 * 32 + lane], v1);
}

extern "C" void kernel_launch(void* const* d_in, const int* in_sizes, int n_in,
                              void* d_out, int out_size) {
    const int*   ids  = (const int*)d_in[0];
    const int*   mask = (const int*)d_in[1];
    const float* W1   = (const float*)d_in[2];
    const float* b1   = (const float*)d_in[3];
    const float* W2   = (const float*)d_in[4];
    const float* b2   = (const float*)d_in[5];
    float* out = (float*)d_out;

    int B = in_sizes[0] / MAX_LEN;

    int lut_pairs  = LUT_DIM * LUT_DIM;
    int pairs_per_block = 8 * LUT_PAIRS_PER_WARP;
    int lut_blocks = (lut_pairs + pairs_per_block - 1) / pairs_per_block;
    build_lut_kernel<<<lut_blocks, 256>>>(W1, b1, W2, b2);

    int rows_per_block = WARPS_PER_BLOCK * ROWS_PER_WARP;
    int blocks = (B + rows_per_block - 1) / rows_per_block;
    feat_kernel<<<blocks, WARPS_PER_BLOCK * 32>>>(ids, mask, out, B);
}